// round 2
// baseline (speedup 1.0000x reference)
#include <cuda_runtime.h>
#include <cstdint>

// VeroneseDecoding: per-row 4x4 symmetric top-eigenvector (Jacobi) + fused
// 64->256 (ReLU) -> 60 MLP using packed f32x2 FMAs, weights broadcast from SMEM.

#define HID   256
#define INF   64
#define OUTM  60
#define TPB   256
#define SW1_STRIDE 68   // padded row (floats) for the transposed W1 tile

static constexpr int SMEM_FLOATS = HID * SW1_STRIDE + HID * 64 + HID + 64;
static constexpr int SMEM_BYTES  = SMEM_FLOATS * 4;

// ---------- packed f32x2 helpers (Blackwell sm_103a) ----------
static __device__ __forceinline__ unsigned long long pk2(float lo, float hi) {
    unsigned long long r;
    asm("mov.b64 %0, {%1, %2};" : "=l"(r) : "f"(lo), "f"(hi));
    return r;
}
static __device__ __forceinline__ void upk2(unsigned long long v, float& lo, float& hi) {
    asm("mov.b64 {%0, %1}, %2;" : "=f"(lo), "=f"(hi) : "l"(v));
}
static __device__ __forceinline__ unsigned long long fma2(unsigned long long a,
                                                          unsigned long long b,
                                                          unsigned long long c) {
    unsigned long long d;
    asm("fma.rn.f32x2 %0, %1, %2, %3;" : "=l"(d) : "l"(a), "l"(b), "l"(c));
    return d;
}
static __device__ __forceinline__ unsigned long long add2(unsigned long long a,
                                                          unsigned long long b) {
    unsigned long long d;
    asm("add.rn.f32x2 %0, %1, %2;" : "=l"(d) : "l"(a), "l"(b));
    return d;
}

// ---------- one Jacobi rotation on pair (P,Q), compile-time indices ----------
template <int P, int Q>
static __device__ __forceinline__ void jrot(float (&A)[4][4], float (&V)[4][4]) {
    float apq = A[P][Q];
    if (fabsf(apq) > 1e-12f) {
        float app = A[P][P], aqq = A[Q][Q];
        float tau = (aqq - app) / (2.0f * apq);
        float t = copysignf(1.0f, tau) / (fabsf(tau) + sqrtf(1.0f + tau * tau));
        float c = rsqrtf(1.0f + t * t);
        float s = t * c;
        A[P][P] = app - t * apq;
        A[Q][Q] = aqq + t * apq;
        A[P][Q] = 0.0f;
        A[Q][P] = 0.0f;
        #pragma unroll
        for (int k = 0; k < 4; k++) {
            if (k == P || k == Q) continue;
            float akp = A[k][P], akq = A[k][Q];
            float np = c * akp - s * akq;
            float nq = s * akp + c * akq;
            A[k][P] = np; A[P][k] = np;
            A[k][Q] = nq; A[Q][k] = nq;
        }
        #pragma unroll
        for (int k = 0; k < 4; k++) {
            float vkp = V[k][P], vkq = V[k][Q];
            V[k][P] = c * vkp - s * vkq;
            V[k][Q] = s * vkp + c * vkq;
        }
    }
}

__global__ void __launch_bounds__(TPB, 1)
vdec_kernel(const float* __restrict__ z,
            const float* __restrict__ W1,
            const float* __restrict__ b1,
            const float* __restrict__ W2,
            const float* __restrict__ b2,
            float* __restrict__ out,
            int B) {
    extern __shared__ float sm[];
    float* sW1 = sm;                          // [256][68]  transposed W1 (W1T[j][k])
    float* sW2 = sm + HID * SW1_STRIDE;       // [256][64]  W2 rows, padded to 64
    float* sb1 = sW2 + HID * 64;              // [256]
    float* sb2 = sb1 + HID;                   // [64] (60 used)

    const int tid = threadIdx.x;

    // Cooperative weight staging (gmem reads coalesced; broadcast reads later
    // make SMEM bank layout irrelevant for the hot loop).
    for (int idx = tid; idx < INF * HID; idx += TPB) {
        int k = idx >> 8;        // idx = k*256 + j  (coalesced over j)
        int j = idx & 255;
        sW1[j * SW1_STRIDE + k] = W1[idx];
    }
    for (int idx = tid; idx < HID * OUTM; idx += TPB) {
        int j = idx / OUTM;
        int o = idx - j * OUTM;
        sW2[j * 64 + o] = W2[idx];
    }
    if (tid < HID)  sb1[tid] = b1[tid];
    if (tid < OUTM) sb2[tid] = b2[tid];
    __syncthreads();

    const int row = blockIdx.x * TPB + tid;
    if (row >= B) return;

    // ---- load this row of z; pack into f32x2 pairs; stash first 10 for eigen
    unsigned long long zp[32];
    float jz[10];
    const float4* zr4 = (const float4*)(z + (size_t)row * INF);
    #pragma unroll
    for (int i = 0; i < 16; i++) {
        float4 v = zr4[i];
        zp[2 * i]     = pk2(v.x, v.y);
        zp[2 * i + 1] = pk2(v.z, v.w);
        if (i == 0)      { jz[0] = v.x; jz[1] = v.y; jz[2] = v.z; jz[3] = v.w; }
        else if (i == 1) { jz[4] = v.x; jz[5] = v.y; jz[6] = v.z; jz[7] = v.w; }
        else if (i == 2) { jz[8] = v.x; jz[9] = v.y; }
    }

    // ---- 4x4 symmetric eigen via cyclic Jacobi (6 sweeps, fully converged)
    float A[4][4], V[4][4];
    A[0][0] = jz[0];
    A[0][1] = A[1][0] = jz[1];
    A[0][2] = A[2][0] = jz[2];
    A[0][3] = A[3][0] = jz[3];
    A[1][1] = jz[4];
    A[1][2] = A[2][1] = jz[5];
    A[1][3] = A[3][1] = jz[6];
    A[2][2] = jz[7];
    A[2][3] = A[3][2] = jz[8];
    A[3][3] = jz[9];
    #pragma unroll
    for (int i = 0; i < 4; i++)
        #pragma unroll
        for (int jj = 0; jj < 4; jj++)
            V[i][jj] = (i == jj) ? 1.0f : 0.0f;

    #pragma unroll
    for (int sweep = 0; sweep < 6; sweep++) {
        jrot<0, 1>(A, V); jrot<0, 2>(A, V); jrot<0, 3>(A, V);
        jrot<1, 2>(A, V); jrot<1, 3>(A, V); jrot<2, 3>(A, V);
    }

    // pick eigenvector of max eigenvalue (predicated selects, no runtime index)
    float best = A[0][0];
    float q0 = V[0][0], q1 = V[1][0], q2 = V[2][0], q3 = V[3][0];
    if (A[1][1] > best) { best = A[1][1]; q0 = V[0][1]; q1 = V[1][1]; q2 = V[2][1]; q3 = V[3][1]; }
    if (A[2][2] > best) { best = A[2][2]; q0 = V[0][2]; q1 = V[1][2]; q2 = V[2][2]; q3 = V[3][2]; }
    if (A[3][3] > best) { best = A[3][3]; q0 = V[0][3]; q1 = V[1][3]; q2 = V[2][3]; q3 = V[3][3]; }
    float sg = (q0 < 0.0f) ? -1.0f : 1.0f;   // sign(0) -> +1, matches reference
    q0 *= sg; q1 *= sg; q2 *= sg; q3 *= sg;

    // ---- fused MLP: h = relu(z @ W1 + b1); out[4:] = h @ W2 + b2
    unsigned long long acc[30];
    #pragma unroll
    for (int i = 0; i < 30; i++) acc[i] = pk2(sb2[2 * i], sb2[2 * i + 1]);

    // Prefetch pipeline: W1 row j is loaded while row j-1's W2 accumulate runs.
    ulonglong2 wbuf[4];
    {
        const ulonglong2* w1p0 = (const ulonglong2*)sW1;
        wbuf[0] = w1p0[0]; wbuf[1] = w1p0[1];
        wbuf[2] = w1p0[2]; wbuf[3] = w1p0[3];
    }
    float bias = sb1[0];

    #pragma unroll 2
    for (int j = 0; j < HID; j++) {
        const ulonglong2* w1p = (const ulonglong2*)(sW1 + j * SW1_STRIDE);
        unsigned long long a0 = 0ull, a1 = 0ull, a2 = 0ull, a3 = 0ull;
        // first 2 f32x2x2 groups come from the prefetch buffer
        a0 = fma2(zp[0], wbuf[0].x, a0);
        a1 = fma2(zp[1], wbuf[0].y, a1);
        a2 = fma2(zp[2], wbuf[1].x, a2);
        a3 = fma2(zp[3], wbuf[1].y, a3);
        a0 = fma2(zp[4], wbuf[2].x, a0);
        a1 = fma2(zp[5], wbuf[2].y, a1);
        a2 = fma2(zp[6], wbuf[3].x, a2);
        a3 = fma2(zp[7], wbuf[3].y, a3);
        #pragma unroll
        for (int i = 2; i < 8; i++) {
            ulonglong2 wA = w1p[2 * i];
            ulonglong2 wB = w1p[2 * i + 1];
            a0 = fma2(zp[4 * i + 0], wA.x, a0);
            a1 = fma2(zp[4 * i + 1], wA.y, a1);
            a2 = fma2(zp[4 * i + 2], wB.x, a2);
            a3 = fma2(zp[4 * i + 3], wB.y, a3);
        }
        unsigned long long t = add2(add2(a0, a1), add2(a2, a3));
        float lo, hi;
        upk2(t, lo, hi);
        float h = bias + lo + hi;
        h = fmaxf(h, 0.0f);
        unsigned long long h2 = pk2(h, h);

        // kick off next row's prefetch before the W2 accumulate tail
        if (j + 1 < HID) {
            const ulonglong2* w1n = (const ulonglong2*)(sW1 + (j + 1) * SW1_STRIDE);
            wbuf[0] = w1n[0]; wbuf[1] = w1n[1];
            wbuf[2] = w1n[2]; wbuf[3] = w1n[3];
            bias = sb1[j + 1];
        }

        const ulonglong2* w2p = (const ulonglong2*)(sW2 + j * 64);
        #pragma unroll
        for (int i = 0; i < 15; i++) {
            ulonglong2 w = w2p[i];
            acc[2 * i]     = fma2(h2, w.x, acc[2 * i]);
            acc[2 * i + 1] = fma2(h2, w.y, acc[2 * i + 1]);
        }
    }

    // ---- write: [q0..q3, acc[0..59]] as 16 float4 stores
    float4* orow = (float4*)(out + (size_t)row * 64);
    float4 qv;
    qv.x = q0; qv.y = q1; qv.z = q2; qv.w = q3;
    orow[0] = qv;
    #pragma unroll
    for (int i = 0; i < 15; i++) {
        float4 v;
        upk2(acc[2 * i],     v.x, v.y);
        upk2(acc[2 * i + 1], v.z, v.w);
        orow[i + 1] = v;
    }
}

extern "C" void kernel_launch(void* const* d_in, const int* in_sizes, int n_in,
                              void* d_out, int out_size) {
    const float* z  = (const float*)d_in[0];
    const float* W1 = (const float*)d_in[1];
    const float* b1 = (const float*)d_in[2];
    const float* W2 = (const float*)d_in[3];
    const float* b2 = (const float*)d_in[4];
    float* out = (float*)d_out;

    const int B = in_sizes[0] / INF;

    cudaFuncSetAttribute(vdec_kernel,
                         cudaFuncAttributeMaxDynamicSharedMemorySize, SMEM_BYTES);

    const int grid = (B + TPB - 1) / TPB;
    vdec_kernel<<<grid, TPB, SMEM_BYTES>>>(z, W1, b1, W2, b2, out, B);
}

// round 5
// speedup vs baseline: 1.3850x; 1.3850x over previous
#include <cuda_runtime.h>
#include <cstdint>

// VeroneseDecoding: Jacobi 4x4 top-eigenvector + tiled two-stage MLP GEMM.
// CTA = 256 rows, 8x8 register tile per thread in both GEMMs (L1-pressure fix
// for R2's 82.7% L1). This rev adds: (a) bank-rotation of the sH transpose
// store (was 8-way conflicted since 8*SZS==0 mod 32) with a matching W2 row
// permutation, (b) +4-float shift of weight column-groups >=32 into the row
// pad to kill the 2-way weight-load conflict.

#define TPB 256
#define RPC 256          // rows per CTA
#define SZS 260          // sZ / sH stride in floats
#define SWS 68           // weight-chunk stride in floats (64 + 4 pad used by shift)

typedef unsigned long long ull;

static constexpr int OFF_Z  = 0;
static constexpr int OFF_H  = OFF_Z  + 64 * SZS;
static constexpr int OFF_W1 = OFF_H  + 64 * SZS;
static constexpr int OFF_W2 = OFF_W1 + 64 * SWS;
static constexpr int OFF_B1 = OFF_W2 + 64 * SWS;
static constexpr int OFF_B2 = OFF_B1 + 64;
static constexpr int SMEM_FLOATS = OFF_B2 + 64;
static constexpr int SMEM_BYTES  = SMEM_FLOATS * 4;

// column offset shift: +4 floats for column index >= 32 (bank de-conflict)
static __device__ __forceinline__ int wshift(int o) { return o + ((o >> 5) << 2); }
// hidden-row permutation matching the sH store rotation
static __device__ __forceinline__ int hperm(int j) {
    return (j & ~7) | (((j & 7) + (j >> 3)) & 7);
}

// ---------- packed f32x2 helpers ----------
static __device__ __forceinline__ ull pk2(float lo, float hi) {
    ull r; asm("mov.b64 %0, {%1, %2};" : "=l"(r) : "f"(lo), "f"(hi)); return r;
}
static __device__ __forceinline__ void upk2(ull v, float& lo, float& hi) {
    asm("mov.b64 {%0, %1}, %2;" : "=f"(lo), "=f"(hi) : "l"(v));
}
static __device__ __forceinline__ ull fma2(ull a, ull b, ull c) {
    ull d; asm("fma.rn.f32x2 %0, %1, %2, %3;" : "=l"(d) : "l"(a), "l"(b), "l"(c)); return d;
}

// ---------- Jacobi rotation, compile-time pair ----------
template <int P, int Q>
static __device__ __forceinline__ void jrot(float (&A)[4][4], float (&V)[4][4]) {
    float apq = A[P][Q];
    if (fabsf(apq) > 1e-12f) {
        float app = A[P][P], aqq = A[Q][Q];
        float tau = (aqq - app) / (2.0f * apq);
        float t = copysignf(1.0f, tau) / (fabsf(tau) + sqrtf(1.0f + tau * tau));
        float c = rsqrtf(1.0f + t * t);
        float s = t * c;
        A[P][P] = app - t * apq;
        A[Q][Q] = aqq + t * apq;
        A[P][Q] = 0.0f; A[Q][P] = 0.0f;
        #pragma unroll
        for (int k = 0; k < 4; k++) {
            if (k == P || k == Q) continue;
            float akp = A[k][P], akq = A[k][Q];
            float np = c * akp - s * akq;
            float nq = s * akp + c * akq;
            A[k][P] = np; A[P][k] = np;
            A[k][Q] = nq; A[Q][k] = nq;
        }
        #pragma unroll
        for (int k = 0; k < 4; k++) {
            float vkp = V[k][P], vkq = V[k][Q];
            V[k][P] = c * vkp - s * vkq;
            V[k][Q] = s * vkp + c * vkq;
        }
    }
}

__global__ void __launch_bounds__(TPB, 1)
vdec_kernel(const float* __restrict__ z,
            const float* __restrict__ W1,
            const float* __restrict__ b1,
            const float* __restrict__ W2,
            const float* __restrict__ b2,
            float* __restrict__ out) {
    extern __shared__ float sm[];
    float* sZ   = sm + OFF_Z;
    float* sH   = sm + OFF_H;
    float* sW1c = sm + OFF_W1;
    float* sW2c = sm + OFF_W2;
    float* sb1c = sm + OFF_B1;
    float* sb2  = sm + OFF_B2;

    const int tid = threadIdx.x;
    const int tc  = tid & 7;    // 8 col groups  x 8 cols
    const int tr  = tid >> 3;   // 32 row groups x 8 rows
    const int csh = wshift(8 * tc);   // bank-shifted column base for weights
    const size_t base = (size_t)blockIdx.x * RPC;

    // ---- stage z transposed: sZ[k][r]
    {
        const float4* z4 = (const float4*)(z + base * 64);
        #pragma unroll
        for (int i = 0; i < 16; i++) {
            int idx = tid + 256 * i;
            float4 v = z4[idx];
            int r = idx >> 4;
            int k = (idx & 15) * 4;
            sZ[(k + 0) * SZS + r] = v.x;
            sZ[(k + 1) * SZS + r] = v.y;
            sZ[(k + 2) * SZS + r] = v.z;
            sZ[(k + 3) * SZS + r] = v.w;
        }
    }
    // ---- stage chunk 0 weights + biases (shift on cols, perm on W2 rows)
    #pragma unroll
    for (int i = 0; i < 4; i++) {
        int idx = tid + 256 * i;
        int k = idx >> 4, cc4 = (idx & 15) * 4;
        float4 v = __ldg((const float4*)(W1 + k * 256 + cc4));
        *(float4*)(sW1c + k * SWS + wshift(cc4)) = v;   // cc4 multiple of 4: shift keeps 16B align
    }
    #pragma unroll
    for (int i = 0; i < 16; i++) {
        int idx = tid + 256 * i;
        int jj = idx >> 6, o = idx & 63;
        sW2c[hperm(jj) * SWS + wshift(o)] = (o < 60) ? __ldg(W2 + jj * 60 + o) : 0.0f;
    }
    if (tid < 64) sb1c[tid] = b1[tid];
    if (tid < 64) sb2[tid]  = (tid < 60) ? b2[tid] : 0.0f;
    __syncthreads();

    // ---- Jacobi eigen for row `tid`
    float q0, q1, q2, q3;
    {
        float jz[10];
        #pragma unroll
        for (int k = 0; k < 10; k++) jz[k] = sZ[k * SZS + tid];
        float A[4][4], V[4][4];
        A[0][0] = jz[0];
        A[0][1] = A[1][0] = jz[1];
        A[0][2] = A[2][0] = jz[2];
        A[0][3] = A[3][0] = jz[3];
        A[1][1] = jz[4];
        A[1][2] = A[2][1] = jz[5];
        A[1][3] = A[3][1] = jz[6];
        A[2][2] = jz[7];
        A[2][3] = A[3][2] = jz[8];
        A[3][3] = jz[9];
        #pragma unroll
        for (int i = 0; i < 4; i++)
            #pragma unroll
            for (int j = 0; j < 4; j++)
                V[i][j] = (i == j) ? 1.0f : 0.0f;
        #pragma unroll
        for (int sweep = 0; sweep < 6; sweep++) {
            jrot<0, 1>(A, V); jrot<0, 2>(A, V); jrot<0, 3>(A, V);
            jrot<1, 2>(A, V); jrot<1, 3>(A, V); jrot<2, 3>(A, V);
        }
        float best = A[0][0];
        q0 = V[0][0]; q1 = V[1][0]; q2 = V[2][0]; q3 = V[3][0];
        if (A[1][1] > best) { best = A[1][1]; q0 = V[0][1]; q1 = V[1][1]; q2 = V[2][1]; q3 = V[3][1]; }
        if (A[2][2] > best) { best = A[2][2]; q0 = V[0][2]; q1 = V[1][2]; q2 = V[2][2]; q3 = V[3][2]; }
        if (A[3][3] > best) { best = A[3][3]; q0 = V[0][3]; q1 = V[1][3]; q2 = V[2][3]; q3 = V[3][3]; }
        float sg = (q0 < 0.0f) ? -1.0f : 1.0f;
        q0 *= sg; q1 *= sg; q2 *= sg; q3 *= sg;
    }

    // ---- persistent out accumulators, b2-init
    ull acc[8][4];
    {
        ulonglong2 b01 = *(const ulonglong2*)(sb2 + 8 * tc);
        ulonglong2 b23 = *(const ulonglong2*)(sb2 + 8 * tc + 4);
        #pragma unroll
        for (int i = 0; i < 8; i++) {
            acc[i][0] = b01.x; acc[i][1] = b01.y;
            acc[i][2] = b23.x; acc[i][3] = b23.y;
        }
    }

    const float* zb  = sZ + 8 * tr;
    const float* hb  = sH + 8 * tr;
    const float* wb  = sW1c + csh;
    const float* w2b = sW2c + csh;

    for (int c = 0; c < 4; c++) {
        // ===== GEMM1: hacc = z @ W1chunk (+b1)
        ull hacc[8][4];
        {
            ulonglong2 b01 = *(const ulonglong2*)(sb1c + 8 * tc);
            ulonglong2 b23 = *(const ulonglong2*)(sb1c + 8 * tc + 4);
            #pragma unroll
            for (int i = 0; i < 8; i++) {
                hacc[i][0] = b01.x; hacc[i][1] = b01.y;
                hacc[i][2] = b23.x; hacc[i][3] = b23.y;
            }
        }
        #pragma unroll 4
        for (int k = 0; k < 64; k++) {
            float4 za = *(const float4*)(zb + k * SZS);
            float4 zc = *(const float4*)(zb + k * SZS + 4);
            ulonglong2 wa = *(const ulonglong2*)(wb + k * SWS);
            ulonglong2 wc = *(const ulonglong2*)(wb + k * SWS + 4);
            ull zd[8];
            zd[0] = pk2(za.x, za.x); zd[1] = pk2(za.y, za.y);
            zd[2] = pk2(za.z, za.z); zd[3] = pk2(za.w, za.w);
            zd[4] = pk2(zc.x, zc.x); zd[5] = pk2(zc.y, zc.y);
            zd[6] = pk2(zc.z, zc.z); zd[7] = pk2(zc.w, zc.w);
            #pragma unroll
            for (int i = 0; i < 8; i++) {
                hacc[i][0] = fma2(zd[i], wa.x, hacc[i][0]);
                hacc[i][1] = fma2(zd[i], wa.y, hacc[i][1]);
                hacc[i][2] = fma2(zd[i], wc.x, hacc[i][2]);
                hacc[i][3] = fma2(zd[i], wc.y, hacc[i][3]);
            }
        }

        // ---- prefetch next chunk's weights into registers
        float4 pf1[4];
        float  pf2[16];
        float  pb1v = 0.0f;
        if (c < 3) {
            const int cn = c + 1;
            #pragma unroll
            for (int i = 0; i < 4; i++) {
                int idx = tid + 256 * i;
                int k = idx >> 4, cc4 = (idx & 15) * 4;
                pf1[i] = __ldg((const float4*)(W1 + k * 256 + cn * 64 + cc4));
            }
            #pragma unroll
            for (int i = 0; i < 16; i++) {
                int idx = tid + 256 * i;
                int jj = idx >> 6, o = idx & 63;
                pf2[i] = (o < 60) ? __ldg(W2 + (cn * 64 + jj) * 60 + o) : 0.0f;
            }
            if (tid < 64) pb1v = b1[cn * 64 + tid];
        }

        // ---- relu + transposed store to sH with tc-rotation (bank-even)
        {
            float hv[8][8];
            #pragma unroll
            for (int i = 0; i < 8; i++) {
                upk2(hacc[i][0], hv[i][0], hv[i][1]);
                upk2(hacc[i][1], hv[i][2], hv[i][3]);
                upk2(hacc[i][2], hv[i][4], hv[i][5]);
                upk2(hacc[i][3], hv[i][6], hv[i][7]);
            }
            #pragma unroll
            for (int i = 0; i < 8; i++)
                #pragma unroll
                for (int j = 0; j < 8; j++)
                    hv[i][j] = fmaxf(hv[i][j], 0.0f);
            #pragma unroll
            for (int cc = 0; cc < 8; cc++) {
                int rrow = 8 * tc + ((cc + tc) & 7);   // == hperm(8*tc+cc)
                float* hp = sH + rrow * SZS + 8 * tr;
                float4 v0; v0.x = hv[0][cc]; v0.y = hv[1][cc]; v0.z = hv[2][cc]; v0.w = hv[3][cc];
                float4 v1; v1.x = hv[4][cc]; v1.y = hv[5][cc]; v1.z = hv[6][cc]; v1.w = hv[7][cc];
                *(float4*)hp = v0;
                *(float4*)(hp + 4) = v1;
            }
        }
        __syncthreads();

        // ===== GEMM2: acc += relu(h) @ W2chunk  (physical hidden rows; both
        // sH and sW2c carry the same hperm permutation, so the sum is exact)
        #pragma unroll 4
        for (int jj = 0; jj < 64; jj++) {
            float4 ha = *(const float4*)(hb + jj * SZS);
            float4 hc = *(const float4*)(hb + jj * SZS + 4);
            ulonglong2 wa = *(const ulonglong2*)(w2b + jj * SWS);
            ulonglong2 wc = *(const ulonglong2*)(w2b + jj * SWS + 4);
            ull hd[8];
            hd[0] = pk2(ha.x, ha.x); hd[1] = pk2(ha.y, ha.y);
            hd[2] = pk2(ha.z, ha.z); hd[3] = pk2(ha.w, ha.w);
            hd[4] = pk2(hc.x, hc.x); hd[5] = pk2(hc.y, hc.y);
            hd[6] = pk2(hc.z, hc.z); hd[7] = pk2(hc.w, hc.w);
            #pragma unroll
            for (int i = 0; i < 8; i++) {
                acc[i][0] = fma2(hd[i], wa.x, acc[i][0]);
                acc[i][1] = fma2(hd[i], wa.y, acc[i][1]);
                acc[i][2] = fma2(hd[i], wc.x, acc[i][2]);
                acc[i][3] = fma2(hd[i], wc.y, acc[i][3]);
            }
        }

        if (c < 3) {
            __syncthreads();
            #pragma unroll
            for (int i = 0; i < 4; i++) {
                int idx = tid + 256 * i;
                int k = idx >> 4, cc4 = (idx & 15) * 4;
                *(float4*)(sW1c + k * SWS + wshift(cc4)) = pf1[i];
            }
            #pragma unroll
            for (int i = 0; i < 16; i++) {
                int idx = tid + 256 * i;
                int jj = idx >> 6, o = idx & 63;
                sW2c[hperm(jj) * SWS + wshift(o)] = pf2[i];
            }
            if (tid < 64) sb1c[tid] = pb1v;
            __syncthreads();
        }
    }

    // ---- writeout
    {
        float4 qv; qv.x = q0; qv.y = q1; qv.z = q2; qv.w = q3;
        *(float4*)(out + (base + tid) * 64) = qv;
    }
    #pragma unroll
    for (int i = 0; i < 8; i++) {
        float* orow = out + (base + 8 * tr + i) * 64 + 4 + 8 * tc;
        float a0, a1, a2, a3, a4, a5, a6, a7;
        upk2(acc[i][0], a0, a1);
        upk2(acc[i][1], a2, a3);
        upk2(acc[i][2], a4, a5);
        upk2(acc[i][3], a6, a7);
        float4 v0; v0.x = a0; v0.y = a1; v0.z = a2; v0.w = a3;
        *(float4*)orow = v0;
        if (tc < 7) {
            float4 v1; v1.x = a4; v1.y = a5; v1.z = a6; v1.w = a7;
            *(float4*)(orow + 4) = v1;
        }
    }
}

extern "C" void kernel_launch(void* const* d_in, const int* in_sizes, int n_in,
                              void* d_out, int out_size) {
    const float* z  = (const float*)d_in[0];
    const float* W1 = (const float*)d_in[1];
    const float* b1 = (const float*)d_in[2];
    const float* W2 = (const float*)d_in[3];
    const float* b2 = (const float*)d_in[4];
    float* out = (float*)d_out;

    const int B = in_sizes[0] / 64;

    cudaFuncSetAttribute(vdec_kernel,
                         cudaFuncAttributeMaxDynamicSharedMemorySize, SMEM_BYTES);

    const int grid = B / RPC;
    vdec_kernel<<<grid, TPB, SMEM_BYTES>>>(z, W1, b1, W2, b2, out);
}